// round 6
// baseline (speedup 1.0000x reference)
#include <cuda_runtime.h>
#include <cuda_bf16.h>

// ---------------------------------------------------------------------------
// 10-qubit state-vector simulator, one warp per batch element, f32x2 packed.
// Amplitude index k (10 bits): bits[9:5]=lane, bits[4:1]=j (reg slot),
// bit[0]=half of a packed 64-bit f32x2 value. Qubit w <-> bit (9-w).
// Circuit: [product state] then 5 x [CNOT layer, merged diagonal G_l, RY layer];
// the final CNOT layer + final diagonal are folded into the readout masks.
// RY gates use tangent form (1 fma2/output); the cos scale products are
// folded into the preceding G diagonals.
// ---------------------------------------------------------------------------

#define NQ 10
#define NL 6
#define BATCH 16384
#define EMB 64

typedef unsigned long long ull;

__device__ float d_G4f[5 * 16 * 32 * 4];  // per (l,j,lane): gr0,gr1,gi0,gi1 (scaled)
__device__ float d_Yt[50];                // (l-1)*10 + w: tan(th/2), l=1..5
__device__ float d_V0[40];                // w*4: cth0, sth0, cph0, sph0

__device__ __forceinline__ ull pack2(float lo, float hi) {
    ull r; asm("mov.b64 %0, {%1,%2};" : "=l"(r) : "f"(lo), "f"(hi)); return r;
}
__device__ __forceinline__ void unpack2(ull v, float& lo, float& hi) {
    asm("mov.b64 {%0,%1}, %2;" : "=f"(lo), "=f"(hi) : "l"(v));
}
__device__ __forceinline__ ull splat2(float x) { return pack2(x, x); }
__device__ __forceinline__ ull fma2(ull a, ull b, ull c) {
    ull d; asm("fma.rn.f32x2 %0, %1, %2, %3;" : "=l"(d) : "l"(a), "l"(b), "l"(c)); return d;
}
__device__ __forceinline__ ull mul2(ull a, ull b) {
    ull d; asm("mul.rn.f32x2 %0, %1, %2;" : "=l"(d) : "l"(a), "l"(b)); return d;
}
__device__ __forceinline__ ull swap64(ull v) {
    float lo, hi; unpack2(v, lo, hi); return pack2(hi, lo);
}
__device__ __forceinline__ ull shx64(ull v, int m) {
    float lo, hi; unpack2(v, lo, hi);
    lo = __shfl_xor_sync(0xffffffffu, lo, m);
    hi = __shfl_xor_sync(0xffffffffu, hi, m);
    return pack2(lo, hi);
}
__device__ __forceinline__ ull shidx64(ull v, int s) {
    float lo, hi; unpack2(v, lo, hi);
    lo = __shfl_sync(0xffffffffu, lo, s);
    hi = __shfl_sync(0xffffffffu, hi, s);
    return pack2(lo, hi);
}
__device__ __forceinline__ float shxf(float v, int m) {
    return __shfl_xor_sync(0xffffffffu, v, m);
}

// ---- prep kernel: diagonals + coefficients --------------------------------
__global__ void prep_kernel(const float* __restrict__ weights) {
    const int t = threadIdx.x;
    if (t < 50) {
        int l = t / 10 + 1, w = t % 10;
        d_Yt[t] = tanf(0.5f * weights[l * 30 + w * 3 + 1]);
    }
    if (t >= 64 && t < 74) {
        int w = t - 64;
        float phi = weights[w * 3 + 0];
        float th  = weights[w * 3 + 1];
        float sth, cth, sph, cph;
        sincosf(0.5f * th, &sth, &cth);
        sincosf(0.5f * phi, &sph, &cph);
        d_V0[w * 4] = cth; d_V0[w * 4 + 1] = sth;
        d_V0[w * 4 + 2] = cph; d_V0[w * 4 + 3] = sph;
    }
    // merged diagonals G_l[k] = Dphi(l+1)[k] * Dom(l)[sigma_l^{-1}(k)],
    // scaled by prod_w cos(th_{l+1,w}/2) (tangent-form compensation for the
    // RY layer that follows G_l).
    const int k = t;  // 1024 threads
    for (int l = 0; l < 5; l++) {
        const int r = l + 1;
        int m = k;
        for (int w = 9; w >= 0; w--) {
            int c = w, tt = (w + r) % 10;
            if ((m >> (9 - c)) & 1) m ^= 1 << (9 - tt);
        }
        float e = 0.f;
        float scale = 1.f;
        for (int w = 0; w < 10; w++) {
            float phi1 = weights[(l + 1) * 30 + w * 3 + 0];
            float om0  = weights[l * 30 + w * 3 + 2];
            e += 0.5f * phi1 * (((k >> (9 - w)) & 1) ? 1.f : -1.f);
            e += 0.5f * om0  * (((m >> (9 - w)) & 1) ? 1.f : -1.f);
            scale *= cosf(0.5f * weights[(l + 1) * 30 + w * 3 + 1]);
        }
        float gi, gr; sincosf(e, &gi, &gr);
        gr *= scale; gi *= scale;
        const int lane = k >> 5, j = (k >> 1) & 15, half = k & 1;
        const int b4 = ((l * 16 + j) * 32 + lane) * 4;
        d_G4f[b4 + half]     = gr;
        d_G4f[b4 + 2 + half] = gi;
    }
}

// ---- tangent-form RY shear on qubit W: out0 = x0 - t*x1, out1 = x1 + t*x0 -
template <int W>
__device__ __forceinline__ void y_gate(ull* vr, ull* vi, int lane, float t) {
    constexpr int BIT = 9 - W;
    if constexpr (BIT >= 5) {
        constexpr int ML = 1 << (BIT - 5);
        const ull SG = splat2((lane & ML) ? t : -t);
#pragma unroll
        for (int j = 0; j < 16; j++) {
            ull pr = shx64(vr[j], ML), pi = shx64(vi[j], ML);
            vr[j] = fma2(SG, pr, vr[j]);
            vi[j] = fma2(SG, pi, vi[j]);
        }
    } else if constexpr (BIT >= 1) {
        constexpr int MJ = 1 << (BIT - 1);
        const ull T = splat2(t), NT = splat2(-t);
#pragma unroll
        for (int j = 0; j < 16; j++) {
            if (!(j & MJ)) {
                const int j1 = j | MJ;
                ull x0r = vr[j], x0i = vi[j], x1r = vr[j1], x1i = vi[j1];
                vr[j]  = fma2(NT, x1r, x0r);
                vi[j]  = fma2(NT, x1i, x0i);
                vr[j1] = fma2(T, x0r, x1r);
                vi[j1] = fma2(T, x0i, x1i);
            }
        }
    } else {
        const ull SP = pack2(-t, t);
#pragma unroll
        for (int j = 0; j < 16; j++) {
            vr[j] = fma2(SP, swap64(vr[j]), vr[j]);
            vi[j] = fma2(SP, swap64(vi[j]), vi[j]);
        }
    }
}

// ---- individual CNOT(C, T) for the middle (reg-target) group --------------
template <int CQ, int TQ>
__device__ __forceinline__ void cnot_p(ull* vr, ull* vi, int lane) {
    constexpr int BC = 9 - CQ, BT = 9 - TQ;
    if constexpr (BC >= 5 && BT >= 1) {
        constexpr int MCL = 1 << (BC - 5), MJ = 1 << (BT - 1);
        const bool ctrl = (lane & MCL) != 0;
#pragma unroll
        for (int j = 0; j < 16; j++) {
            if (!(j & MJ)) {
                const int j1 = j | MJ;
                ull a = vr[j], b = vr[j1];
                vr[j] = ctrl ? b : a; vr[j1] = ctrl ? a : b;
                ull p = vi[j], q = vi[j1];
                vi[j] = ctrl ? q : p; vi[j1] = ctrl ? p : q;
            }
        }
    } else if constexpr (BC >= 5) {
        constexpr int MCL = 1 << (BC - 5);
        const bool ctrl = (lane & MCL) != 0;
#pragma unroll
        for (int j = 0; j < 16; j++) {
            ull rs = swap64(vr[j]), is = swap64(vi[j]);
            vr[j] = ctrl ? rs : vr[j];
            vi[j] = ctrl ? is : vi[j];
        }
    } else if constexpr (BC >= 1 && BT >= 1) {
        constexpr int MJ = 1 << (BC - 1), MT = 1 << (BT - 1);
#pragma unroll
        for (int j = 0; j < 16; j++) {
            if ((j & MJ) && !(j & MT)) {
                const int j1 = j | MT;
                ull t;
                t = vr[j]; vr[j] = vr[j1]; vr[j1] = t;
                t = vi[j]; vi[j] = vi[j1]; vi[j1] = t;
            }
        }
    } else if constexpr (BC >= 1) {
        constexpr int MJ = 1 << (BC - 1);
#pragma unroll
        for (int j = 0; j < 16; j++) {
            if (j & MJ) { vr[j] = swap64(vr[j]); vi[j] = swap64(vi[j]); }
        }
    }
}

// ---- merged leading lane/lane group (CNOT(w,w+R) for w=0..M-1) -----------
template <int R, int M>
__device__ __forceinline__ void cnot_ll_group(ull* vr, ull* vi, int lane) {
    int s = lane;
#pragma unroll
    for (int w = M - 1; w >= 0; w--) {
        s ^= ((s >> (4 - w)) & 1) << (4 - w - R);
    }
#pragma unroll
    for (int j = 0; j < 16; j++) {
        vr[j] = shidx64(vr[j], s);
        vi[j] = shidx64(vi[j], s);
    }
}

// ---- merged trailing reg-ctrl/lane-tgt group ------------------------------
__device__ constexpr int trail_mask_ct(int R, int j, int h) {
    int m = 0;
    for (int w = 5; w <= 9; w++) {
        int t = (w + R) % 10;
        if (w + R >= 10 && t <= 4) {
            int bit = (w == 9) ? h : ((j >> (8 - w)) & 1);
            if (bit) m ^= 16 >> t;
        }
    }
    return m;
}
template <int R, int J>
__device__ __forceinline__ void cnot_trail_j(ull* vr, ull* vi) {
    if constexpr (J < 16) {
        constexpr int mlo = trail_mask_ct(R, J, 0);
        constexpr int mhi = trail_mask_ct(R, J, 1);
        if constexpr (mlo != 0 || mhi != 0) {
            float rlo, rhi, ilo, ihi;
            unpack2(vr[J], rlo, rhi);
            unpack2(vi[J], ilo, ihi);
            if constexpr (mlo != 0) { rlo = shxf(rlo, mlo); ilo = shxf(ilo, mlo); }
            if constexpr (mhi != 0) { rhi = shxf(rhi, mhi); ihi = shxf(ihi, mhi); }
            vr[J] = pack2(rlo, rhi);
            vi[J] = pack2(ilo, ihi);
        }
        cnot_trail_j<R, J + 1>(vr, vi);
    }
}

// ---- middle sequential CNOTs (reg targets) --------------------------------
template <int L, int W, int WEND>
__device__ __forceinline__ void cnots_seq(ull* vr, ull* vi, int lane) {
    if constexpr (W <= WEND) {
        cnot_p<W, (W + L % 9 + 1) % 10>(vr, vi, lane);
        cnots_seq<L, W + 1, WEND>(vr, vi, lane);
    }
}

template <int L>
__device__ __forceinline__ void cnot_layer(ull* vr, ull* vi, int lane) {
    constexpr int R = L + 1;
    if constexpr (R <= 4) cnot_ll_group<R, 5 - R>(vr, vi, lane);
    cnots_seq<L, 5 - R, 9 - R>(vr, vi, lane);
    cnot_trail_j<R, 0>(vr, vi);
}

// ---- merged diagonal pass (-gi via packed sign flip) -----------------------
__device__ __forceinline__ void apply_G(ull* vr, ull* vi,
                                        const ulonglong2* __restrict__ sG,
                                        int base) {
#pragma unroll
    for (int j = 0; j < 16; j++) {
        ulonglong2 g = sG[base + j * 32];
        ull GR = g.x, GI = g.y;
        ull NGI = GI ^ 0x8000000080000000ULL;
        ull nr = fma2(GR, vr[j], mul2(NGI, vi[j]));
        ull ni = fma2(GR, vi[j], mul2(GI, vr[j]));
        vr[j] = nr; vi[j] = ni;
    }
}

// ---- compile-time layer structure -----------------------------------------
template <int L, int W>
__device__ __forceinline__ void y_layer(ull* vr, ull* vi, int lane,
                                        const float* __restrict__ sY) {
    if constexpr (W < NQ) {
        y_gate<W>(vr, vi, lane, sY[(L - 1) * 10 + W]);
        y_layer<L, W + 1>(vr, vi, lane, sY);
    }
}
template <int L>
__device__ __forceinline__ void run_layers(ull* vr, ull* vi, int lane,
                                           const ulonglong2* __restrict__ sG,
                                           const float* __restrict__ sY) {
    if constexpr (L < 5) {
        cnot_layer<L>(vr, vi, lane);
        apply_G(vr, vi, sG, L * 512 + lane);
        y_layer<L + 1, 0>(vr, vi, lane, sY);
        run_layers<L + 1>(vr, vi, lane, sG, sY);
    }
}

__device__ __forceinline__ float wht5(float v, int lane) {
#pragma unroll
    for (int m = 1; m < 32; m <<= 1) {
        float u = shxf(v, m);
        v = (lane & m) ? (u - v) : (u + v);
    }
    return v;
}

// ---- main kernel: 8 warps per block, 1 element per warp -------------------
__global__ void __launch_bounds__(256)
qsim_kernel(const float* __restrict__ x, const float* __restrict__ Wm,
            const float* __restrict__ b, float* __restrict__ out) {
    extern __shared__ float smem[];
    float* sG4f = smem;                 // 10240 floats (ull2 view)
    float* sW   = smem + 10240;         // 640
    float* sY   = smem + 10880;         // 50
    float* sV   = smem + 10930;         // 40
    float* sb   = smem + 10970;         // 16

    const int tid = threadIdx.x;
    {
        float4* d4 = (float4*)sG4f;
        const float4* s4 = (const float4*)d_G4f;
        for (int i = tid; i < 2560; i += 256) d4[i] = s4[i];
        for (int i = tid; i < NQ * EMB; i += 256) sW[i] = Wm[i];
        if (tid < 50) sY[tid] = d_Yt[tid];
        if (tid < 40) sV[tid] = d_V0[tid];
        if (tid < 16) sb[tid] = (tid < NQ) ? b[tid] : 0.f;
    }
    __syncthreads();

    const int lane = tid & 31;
    const int e = blockIdx.x * 8 + (tid >> 5);

    // angles = x[e] @ W.T + b  (half-angles)
    const float xa = x[e * EMB + lane];
    const float xb = x[e * EMB + 32 + lane];
    float halfang[NQ];
#pragma unroll
    for (int w = 0; w < NQ; w++) {
        float p = xa * sW[w * EMB + lane] + xb * sW[w * EMB + 32 + lane];
#pragma unroll
        for (int m = 16; m >= 1; m >>= 1) p += shxf(p, m);
        halfang[w] = 0.5f * (p + sb[w]);
    }

    // per-qubit vectors v_w = RY(th0) RZ(phi0) RX(a) |0>
    float v0r[NQ], v0i[NQ], v1r[NQ], v1i[NQ];
#pragma unroll
    for (int w = 0; w < NQ; w++) {
        float sa, ca; __sincosf(halfang[w], &sa, &ca);
        float cth = sV[w * 4], sth = sV[w * 4 + 1];
        float cph = sV[w * 4 + 2], sph = sV[w * 4 + 3];
        float P = ca * cph, Q = ca * sph, R = sa * cph, T = sa * sph;
        v0r[w] = cth * P - sth * T;
        v0i[w] = sth * R - cth * Q;
        v1r[w] = sth * P + cth * T;
        v1i[w] = -sth * Q - cth * R;
    }

    // lane factor: qubits 0..4 on lane bits 4..0
    float plr = (lane & 16) ? v1r[0] : v0r[0];
    float pli = (lane & 16) ? v1i[0] : v0i[0];
#pragma unroll
    for (int w = 1; w < 5; w++) {
        const int m = 1 << (4 - w);
        float tr = (lane & m) ? v1r[w] : v0r[w];
        float ti = (lane & m) ? v1i[w] : v0i[w];
        float nr = plr * tr - pli * ti;
        float ni = plr * ti + pli * tr;
        plr = nr; pli = ni;
    }

    // register factors: qubits 5..8 on j bits 3..0 (doubling build)
    float rr[16], ri[16];
    rr[0] = v0r[5]; ri[0] = v0i[5];
    rr[8] = v1r[5]; ri[8] = v1i[5];
#pragma unroll
    for (int base = 0; base <= 8; base += 8) {
        float ar = rr[base], ai = ri[base];
        rr[base + 4] = ar * v1r[6] - ai * v1i[6];
        ri[base + 4] = ar * v1i[6] + ai * v1r[6];
        rr[base]     = ar * v0r[6] - ai * v0i[6];
        ri[base]     = ar * v0i[6] + ai * v0r[6];
    }
#pragma unroll
    for (int base = 0; base <= 12; base += 4) {
        float ar = rr[base], ai = ri[base];
        rr[base + 2] = ar * v1r[7] - ai * v1i[7];
        ri[base + 2] = ar * v1i[7] + ai * v1r[7];
        rr[base]     = ar * v0r[7] - ai * v0i[7];
        ri[base]     = ar * v0i[7] + ai * v0r[7];
    }
#pragma unroll
    for (int base = 0; base <= 14; base += 2) {
        float ar = rr[base], ai = ri[base];
        rr[base + 1] = ar * v1r[8] - ai * v1i[8];
        ri[base + 1] = ar * v1i[8] + ai * v1r[8];
        rr[base]     = ar * v0r[8] - ai * v0i[8];
        ri[base]     = ar * v0i[8] + ai * v0r[8];
    }
    // fold the lane factor, then tensor with qubit 9 (packed half)
    ull vr[16], vi[16];
    const ull V9R  = pack2(v0r[9], v1r[9]);
    const ull V9I  = pack2(v0i[9], v1i[9]);
    const ull NV9I = pack2(-v0i[9], -v1i[9]);
#pragma unroll
    for (int j = 0; j < 16; j++) {
        float ar = plr * rr[j] - pli * ri[j];
        float ai = plr * ri[j] + pli * rr[j];
        ull AR = splat2(ar), AI = splat2(ai);
        vr[j] = fma2(AR, V9R, mul2(AI, NV9I));
        vi[j] = fma2(AR, V9I, mul2(AI, V9R));
    }

    // 5 x [CNOT layer, merged (scaled) diagonal, tangent RY layer]
    run_layers<0>(vr, vi, lane, (const ulonglong2*)sG4f, sY);

    // readout with sigma_5-adjusted Walsh masks
    float a0 = 0.f, a1 = 0.f, a2 = 0.f, a3 = 0.f, a4 = 0.f, a5 = 0.f, a6 = 0.f;
#pragma unroll
    for (int j = 0; j < 16; j++) {
        ull p2 = fma2(vr[j], vr[j], mul2(vi[j], vi[j]));
        float plo, phi_; unpack2(p2, plo, phi_);
        float s = plo + phi_;
        float d = plo - phi_;
        a0 += s;
        a1 += (j & 8) ? -s : s;
        a2 += (j & 4) ? -s : s;
        a3 += (j & 2) ? -s : s;
        a4 += (j & 1) ? -s : s;
        a5 += (j & 8) ? -d : d;
        a6 += d;
    }
    a0 = wht5(a0, lane);
    a1 = wht5(a1, lane);
    a2 = wht5(a2, lane);
    a3 = wht5(a3, lane);
    a4 = wht5(a4, lane);
    a5 = wht5(a5, lane);
    a6 = wht5(a6, lane);

    float* o = out + e * NQ;
    if (lane == 17) o[0] = a0;                 // q0: L={4,0}
    if (lane == 8)  { o[1] = a1; o[7] = a3; }  // q1: L={3},J=8 ; q7: L={3},J=2
    if (lane == 20) o[2] = a2;                 // q2: L={4,2},J=4
    if (lane == 10) o[3] = a3;                 // q3: L={3,1},J=2
    if (lane == 5)  o[4] = a4;                 // q4: L={2,0},J=1
    if (lane == 2)  { o[5] = a5; o[9] = a6; }  // q5: L={1},J=8,H ; q9: L={1},H
    if (lane == 16) o[6] = a2;                 // q6: L={4},J=4
    if (lane == 4)  o[8] = a4;                 // q8: L={2},J=1
}

extern "C" void kernel_launch(void* const* d_in, const int* in_sizes, int n_in,
                              void* d_out, int out_size) {
    const float* x       = (const float*)d_in[0];  // (16384, 64)
    const float* Wm      = (const float*)d_in[1];  // (10, 64)
    const float* b       = (const float*)d_in[2];  // (10,)
    const float* weights = (const float*)d_in[3];  // (6, 10, 3)
    float* out = (float*)d_out;                    // (16384, 10)

    const int smem_bytes = (10970 + 16) * sizeof(float);
    cudaFuncSetAttribute(qsim_kernel,
                         cudaFuncAttributeMaxDynamicSharedMemorySize, smem_bytes);

    prep_kernel<<<1, 1024>>>(weights);
    qsim_kernel<<<BATCH / 8, 256, smem_bytes>>>(x, Wm, b, out);
}

// round 7
// speedup vs baseline: 1.1772x; 1.1772x over previous
#include <cuda_runtime.h>
#include <cuda_bf16.h>

// ---------------------------------------------------------------------------
// 10-qubit state-vector simulator, one warp per batch element, f32x2 packed.
// Amplitude index k (10 bits): bits[9:5]=lane, bits[4:1]=j (reg slot),
// bit[0]=half of a packed 64-bit f32x2 value. Qubit w <-> bit (9-w).
// Circuit: [product state] then 5 x [CNOT layer, merged diagonal G_l, RY layer];
// the final CNOT layer + final diagonal are folded into the readout masks.
// RY gates use tangent form (1 fma2/output); the cos scale products are
// folded into the preceding G diagonals. __launch_bounds__(256,2) pins
// regs <= 128 so 2 blocks stay resident per SM (the R5 regression was a
// 132-reg allocation dropping occupancy to 1 block/SM).
// ---------------------------------------------------------------------------

#define NQ 10
#define NL 6
#define BATCH 16384
#define EMB 64

typedef unsigned long long ull;

__device__ float d_G4f[5 * 16 * 32 * 4];  // per (l,j,lane): gr0,gr1,gi0,gi1 (scaled)
__device__ float d_Yt[50];                // (l-1)*10 + w: tan(th/2), l=1..5
__device__ float d_V0[40];                // w*4: cth0, sth0, cph0, sph0

__device__ __forceinline__ ull pack2(float lo, float hi) {
    ull r; asm("mov.b64 %0, {%1,%2};" : "=l"(r) : "f"(lo), "f"(hi)); return r;
}
__device__ __forceinline__ void unpack2(ull v, float& lo, float& hi) {
    asm("mov.b64 {%0,%1}, %2;" : "=f"(lo), "=f"(hi) : "l"(v));
}
__device__ __forceinline__ ull splat2(float x) { return pack2(x, x); }
__device__ __forceinline__ ull fma2(ull a, ull b, ull c) {
    ull d; asm("fma.rn.f32x2 %0, %1, %2, %3;" : "=l"(d) : "l"(a), "l"(b), "l"(c)); return d;
}
__device__ __forceinline__ ull mul2(ull a, ull b) {
    ull d; asm("mul.rn.f32x2 %0, %1, %2;" : "=l"(d) : "l"(a), "l"(b)); return d;
}
__device__ __forceinline__ ull swap64(ull v) {
    float lo, hi; unpack2(v, lo, hi); return pack2(hi, lo);
}
__device__ __forceinline__ ull shx64(ull v, int m) {
    float lo, hi; unpack2(v, lo, hi);
    lo = __shfl_xor_sync(0xffffffffu, lo, m);
    hi = __shfl_xor_sync(0xffffffffu, hi, m);
    return pack2(lo, hi);
}
__device__ __forceinline__ ull shidx64(ull v, int s) {
    float lo, hi; unpack2(v, lo, hi);
    lo = __shfl_sync(0xffffffffu, lo, s);
    hi = __shfl_sync(0xffffffffu, hi, s);
    return pack2(lo, hi);
}
__device__ __forceinline__ float shxf(float v, int m) {
    return __shfl_xor_sync(0xffffffffu, v, m);
}

// ---- prep kernel: diagonals + coefficients --------------------------------
__global__ void prep_kernel(const float* __restrict__ weights) {
    const int t = threadIdx.x;
    if (t < 50) {
        int l = t / 10 + 1, w = t % 10;
        d_Yt[t] = tanf(0.5f * weights[l * 30 + w * 3 + 1]);
    }
    if (t >= 64 && t < 74) {
        int w = t - 64;
        float phi = weights[w * 3 + 0];
        float th  = weights[w * 3 + 1];
        float sth, cth, sph, cph;
        sincosf(0.5f * th, &sth, &cth);
        sincosf(0.5f * phi, &sph, &cph);
        d_V0[w * 4] = cth; d_V0[w * 4 + 1] = sth;
        d_V0[w * 4 + 2] = cph; d_V0[w * 4 + 3] = sph;
    }
    // merged diagonals G_l[k] = Dphi(l+1)[k] * Dom(l)[sigma_l^{-1}(k)],
    // scaled by prod_w cos(th_{l+1,w}/2) (tangent-form compensation).
    const int k = t;  // 1024 threads
    for (int l = 0; l < 5; l++) {
        const int r = l + 1;
        int m = k;
        for (int w = 9; w >= 0; w--) {
            int c = w, tt = (w + r) % 10;
            if ((m >> (9 - c)) & 1) m ^= 1 << (9 - tt);
        }
        float e = 0.f;
        float scale = 1.f;
        for (int w = 0; w < 10; w++) {
            float phi1 = weights[(l + 1) * 30 + w * 3 + 0];
            float om0  = weights[l * 30 + w * 3 + 2];
            e += 0.5f * phi1 * (((k >> (9 - w)) & 1) ? 1.f : -1.f);
            e += 0.5f * om0  * (((m >> (9 - w)) & 1) ? 1.f : -1.f);
            scale *= cosf(0.5f * weights[(l + 1) * 30 + w * 3 + 1]);
        }
        float gi, gr; sincosf(e, &gi, &gr);
        gr *= scale; gi *= scale;
        const int lane = k >> 5, j = (k >> 1) & 15, half = k & 1;
        const int b4 = ((l * 16 + j) * 32 + lane) * 4;
        d_G4f[b4 + half]     = gr;
        d_G4f[b4 + 2 + half] = gi;
    }
}

// ---- tangent-form RY shear on qubit W: out0 = x0 - t*x1, out1 = x1 + t*x0 -
template <int W>
__device__ __forceinline__ void y_gate(ull* vr, ull* vi, int lane, float t) {
    constexpr int BIT = 9 - W;
    if constexpr (BIT >= 5) {
        constexpr int ML = 1 << (BIT - 5);
        const ull SG = splat2((lane & ML) ? t : -t);
#pragma unroll
        for (int j = 0; j < 16; j++) {
            ull pr = shx64(vr[j], ML), pi = shx64(vi[j], ML);
            vr[j] = fma2(SG, pr, vr[j]);
            vi[j] = fma2(SG, pi, vi[j]);
        }
    } else if constexpr (BIT >= 1) {
        constexpr int MJ = 1 << (BIT - 1);
        const ull T = splat2(t), NT = splat2(-t);
#pragma unroll
        for (int j = 0; j < 16; j++) {
            if (!(j & MJ)) {
                const int j1 = j | MJ;
                ull x0r = vr[j], x0i = vi[j], x1r = vr[j1], x1i = vi[j1];
                vr[j]  = fma2(NT, x1r, x0r);
                vi[j]  = fma2(NT, x1i, x0i);
                vr[j1] = fma2(T, x0r, x1r);
                vi[j1] = fma2(T, x0i, x1i);
            }
        }
    } else {
        const ull SP = pack2(-t, t);
#pragma unroll
        for (int j = 0; j < 16; j++) {
            vr[j] = fma2(SP, swap64(vr[j]), vr[j]);
            vi[j] = fma2(SP, swap64(vi[j]), vi[j]);
        }
    }
}

// ---- individual CNOT(C, T) for the middle (reg-target) group --------------
template <int CQ, int TQ>
__device__ __forceinline__ void cnot_p(ull* vr, ull* vi, int lane) {
    constexpr int BC = 9 - CQ, BT = 9 - TQ;
    if constexpr (BC >= 5 && BT >= 1) {
        constexpr int MCL = 1 << (BC - 5), MJ = 1 << (BT - 1);
        const bool ctrl = (lane & MCL) != 0;
#pragma unroll
        for (int j = 0; j < 16; j++) {
            if (!(j & MJ)) {
                const int j1 = j | MJ;
                ull a = vr[j], b = vr[j1];
                vr[j] = ctrl ? b : a; vr[j1] = ctrl ? a : b;
                ull p = vi[j], q = vi[j1];
                vi[j] = ctrl ? q : p; vi[j1] = ctrl ? p : q;
            }
        }
    } else if constexpr (BC >= 5) {
        constexpr int MCL = 1 << (BC - 5);
        const bool ctrl = (lane & MCL) != 0;
#pragma unroll
        for (int j = 0; j < 16; j++) {
            ull rs = swap64(vr[j]), is = swap64(vi[j]);
            vr[j] = ctrl ? rs : vr[j];
            vi[j] = ctrl ? is : vi[j];
        }
    } else if constexpr (BC >= 1 && BT >= 1) {
        constexpr int MJ = 1 << (BC - 1), MT = 1 << (BT - 1);
#pragma unroll
        for (int j = 0; j < 16; j++) {
            if ((j & MJ) && !(j & MT)) {
                const int j1 = j | MT;
                ull t;
                t = vr[j]; vr[j] = vr[j1]; vr[j1] = t;
                t = vi[j]; vi[j] = vi[j1]; vi[j1] = t;
            }
        }
    } else if constexpr (BC >= 1) {
        constexpr int MJ = 1 << (BC - 1);
#pragma unroll
        for (int j = 0; j < 16; j++) {
            if (j & MJ) { vr[j] = swap64(vr[j]); vi[j] = swap64(vi[j]); }
        }
    }
}

// ---- merged leading lane/lane group (CNOT(w,w+R) for w=0..M-1) -----------
template <int R, int M>
__device__ __forceinline__ void cnot_ll_group(ull* vr, ull* vi, int lane) {
    int s = lane;
#pragma unroll
    for (int w = M - 1; w >= 0; w--) {
        s ^= ((s >> (4 - w)) & 1) << (4 - w - R);
    }
#pragma unroll
    for (int j = 0; j < 16; j++) {
        vr[j] = shidx64(vr[j], s);
        vi[j] = shidx64(vi[j], s);
    }
}

// ---- merged trailing reg-ctrl/lane-tgt group ------------------------------
__device__ constexpr int trail_mask_ct(int R, int j, int h) {
    int m = 0;
    for (int w = 5; w <= 9; w++) {
        int t = (w + R) % 10;
        if (w + R >= 10 && t <= 4) {
            int bit = (w == 9) ? h : ((j >> (8 - w)) & 1);
            if (bit) m ^= 16 >> t;
        }
    }
    return m;
}
template <int R, int J>
__device__ __forceinline__ void cnot_trail_j(ull* vr, ull* vi) {
    if constexpr (J < 16) {
        constexpr int mlo = trail_mask_ct(R, J, 0);
        constexpr int mhi = trail_mask_ct(R, J, 1);
        if constexpr (mlo != 0 || mhi != 0) {
            float rlo, rhi, ilo, ihi;
            unpack2(vr[J], rlo, rhi);
            unpack2(vi[J], ilo, ihi);
            if constexpr (mlo != 0) { rlo = shxf(rlo, mlo); ilo = shxf(ilo, mlo); }
            if constexpr (mhi != 0) { rhi = shxf(rhi, mhi); ihi = shxf(ihi, mhi); }
            vr[J] = pack2(rlo, rhi);
            vi[J] = pack2(ilo, ihi);
        }
        cnot_trail_j<R, J + 1>(vr, vi);
    }
}

// ---- middle sequential CNOTs (reg targets) --------------------------------
template <int L, int W, int WEND>
__device__ __forceinline__ void cnots_seq(ull* vr, ull* vi, int lane) {
    if constexpr (W <= WEND) {
        cnot_p<W, (W + L % 9 + 1) % 10>(vr, vi, lane);
        cnots_seq<L, W + 1, WEND>(vr, vi, lane);
    }
}

template <int L>
__device__ __forceinline__ void cnot_layer(ull* vr, ull* vi, int lane) {
    constexpr int R = L + 1;
    if constexpr (R <= 4) cnot_ll_group<R, 5 - R>(vr, vi, lane);
    cnots_seq<L, 5 - R, 9 - R>(vr, vi, lane);
    cnot_trail_j<R, 0>(vr, vi);
}

// ---- merged diagonal pass (-gi via packed sign flip) -----------------------
__device__ __forceinline__ void apply_G(ull* vr, ull* vi,
                                        const ulonglong2* __restrict__ sG,
                                        int base) {
#pragma unroll
    for (int j = 0; j < 16; j++) {
        ulonglong2 g = sG[base + j * 32];
        ull GR = g.x, GI = g.y;
        ull NGI = GI ^ 0x8000000080000000ULL;
        ull nr = fma2(GR, vr[j], mul2(NGI, vi[j]));
        ull ni = fma2(GR, vi[j], mul2(GI, vr[j]));
        vr[j] = nr; vi[j] = ni;
    }
}

// ---- compile-time layer structure -----------------------------------------
template <int L, int W>
__device__ __forceinline__ void y_layer(ull* vr, ull* vi, int lane,
                                        const float* __restrict__ sY) {
    if constexpr (W < NQ) {
        y_gate<W>(vr, vi, lane, sY[(L - 1) * 10 + W]);
        y_layer<L, W + 1>(vr, vi, lane, sY);
    }
}
template <int L>
__device__ __forceinline__ void run_layers(ull* vr, ull* vi, int lane,
                                           const ulonglong2* __restrict__ sG,
                                           const float* __restrict__ sY) {
    if constexpr (L < 5) {
        cnot_layer<L>(vr, vi, lane);
        apply_G(vr, vi, sG, L * 512 + lane);
        y_layer<L + 1, 0>(vr, vi, lane, sY);
        run_layers<L + 1>(vr, vi, lane, sG, sY);
    }
}

__device__ __forceinline__ float wht5(float v, int lane) {
#pragma unroll
    for (int m = 1; m < 32; m <<= 1) {
        float u = shxf(v, m);
        v = (lane & m) ? (u - v) : (u + v);
    }
    return v;
}

// ---- main kernel: 8 warps per block, 1 element per warp -------------------
__global__ void __launch_bounds__(256, 2)
qsim_kernel(const float* __restrict__ x, const float* __restrict__ Wm,
            const float* __restrict__ b, float* __restrict__ out) {
    extern __shared__ float smem[];
    float* sG4f = smem;                 // 10240 floats (ull2 view)
    float* sW   = smem + 10240;         // 640
    float* sY   = smem + 10880;         // 50
    float* sV   = smem + 10930;         // 40
    float* sb   = smem + 10970;         // 16

    const int tid = threadIdx.x;
    {
        float4* d4 = (float4*)sG4f;
        const float4* s4 = (const float4*)d_G4f;
        for (int i = tid; i < 2560; i += 256) d4[i] = s4[i];
        for (int i = tid; i < NQ * EMB; i += 256) sW[i] = Wm[i];
        if (tid < 50) sY[tid] = d_Yt[tid];
        if (tid < 40) sV[tid] = d_V0[tid];
        if (tid < 16) sb[tid] = (tid < NQ) ? b[tid] : 0.f;
    }
    __syncthreads();

    const int lane = tid & 31;
    const int e = blockIdx.x * 8 + (tid >> 5);

    // angles = x[e] @ W.T + b  (half-angles)
    const float xa = x[e * EMB + lane];
    const float xb = x[e * EMB + 32 + lane];
    float halfang[NQ];
#pragma unroll
    for (int w = 0; w < NQ; w++) {
        float p = xa * sW[w * EMB + lane] + xb * sW[w * EMB + 32 + lane];
#pragma unroll
        for (int m = 16; m >= 1; m >>= 1) p += shxf(p, m);
        halfang[w] = 0.5f * (p + sb[w]);
    }

    // per-qubit vectors v_w = RY(th0) RZ(phi0) RX(a) |0>
    float v0r[NQ], v0i[NQ], v1r[NQ], v1i[NQ];
#pragma unroll
    for (int w = 0; w < NQ; w++) {
        float sa, ca; __sincosf(halfang[w], &sa, &ca);
        float cth = sV[w * 4], sth = sV[w * 4 + 1];
        float cph = sV[w * 4 + 2], sph = sV[w * 4 + 3];
        float P = ca * cph, Q = ca * sph, R = sa * cph, T = sa * sph;
        v0r[w] = cth * P - sth * T;
        v0i[w] = sth * R - cth * Q;
        v1r[w] = sth * P + cth * T;
        v1i[w] = -sth * Q - cth * R;
    }

    // lane factor: qubits 0..4 on lane bits 4..0
    float plr = (lane & 16) ? v1r[0] : v0r[0];
    float pli = (lane & 16) ? v1i[0] : v0i[0];
#pragma unroll
    for (int w = 1; w < 5; w++) {
        const int m = 1 << (4 - w);
        float tr = (lane & m) ? v1r[w] : v0r[w];
        float ti = (lane & m) ? v1i[w] : v0i[w];
        float nr = plr * tr - pli * ti;
        float ni = plr * ti + pli * tr;
        plr = nr; pli = ni;
    }

    // register factors: qubits 5..8 on j bits 3..0 (doubling build)
    float rr[16], ri[16];
    rr[0] = v0r[5]; ri[0] = v0i[5];
    rr[8] = v1r[5]; ri[8] = v1i[5];
#pragma unroll
    for (int base = 0; base <= 8; base += 8) {
        float ar = rr[base], ai = ri[base];
        rr[base + 4] = ar * v1r[6] - ai * v1i[6];
        ri[base + 4] = ar * v1i[6] + ai * v1r[6];
        rr[base]     = ar * v0r[6] - ai * v0i[6];
        ri[base]     = ar * v0i[6] + ai * v0r[6];
    }
#pragma unroll
    for (int base = 0; base <= 12; base += 4) {
        float ar = rr[base], ai = ri[base];
        rr[base + 2] = ar * v1r[7] - ai * v1i[7];
        ri[base + 2] = ar * v1i[7] + ai * v1r[7];
        rr[base]     = ar * v0r[7] - ai * v0i[7];
        ri[base]     = ar * v0i[7] + ai * v0r[7];
    }
#pragma unroll
    for (int base = 0; base <= 14; base += 2) {
        float ar = rr[base], ai = ri[base];
        rr[base + 1] = ar * v1r[8] - ai * v1i[8];
        ri[base + 1] = ar * v1i[8] + ai * v1r[8];
        rr[base]     = ar * v0r[8] - ai * v0i[8];
        ri[base]     = ar * v0i[8] + ai * v0r[8];
    }
    // fold the lane factor, then tensor with qubit 9 (packed half)
    ull vr[16], vi[16];
    const ull V9R  = pack2(v0r[9], v1r[9]);
    const ull V9I  = pack2(v0i[9], v1i[9]);
    const ull NV9I = pack2(-v0i[9], -v1i[9]);
#pragma unroll
    for (int j = 0; j < 16; j++) {
        float ar = plr * rr[j] - pli * ri[j];
        float ai = plr * ri[j] + pli * rr[j];
        ull AR = splat2(ar), AI = splat2(ai);
        vr[j] = fma2(AR, V9R, mul2(AI, NV9I));
        vi[j] = fma2(AR, V9I, mul2(AI, V9R));
    }

    // 5 x [CNOT layer, merged (scaled) diagonal, tangent RY layer]
    run_layers<0>(vr, vi, lane, (const ulonglong2*)sG4f, sY);

    // readout with sigma_5-adjusted Walsh masks
    float a0 = 0.f, a1 = 0.f, a2 = 0.f, a3 = 0.f, a4 = 0.f, a5 = 0.f, a6 = 0.f;
#pragma unroll
    for (int j = 0; j < 16; j++) {
        ull p2 = fma2(vr[j], vr[j], mul2(vi[j], vi[j]));
        float plo, phi_; unpack2(p2, plo, phi_);
        float s = plo + phi_;
        float d = plo - phi_;
        a0 += s;
        a1 += (j & 8) ? -s : s;
        a2 += (j & 4) ? -s : s;
        a3 += (j & 2) ? -s : s;
        a4 += (j & 1) ? -s : s;
        a5 += (j & 8) ? -d : d;
        a6 += d;
    }
    a0 = wht5(a0, lane);
    a1 = wht5(a1, lane);
    a2 = wht5(a2, lane);
    a3 = wht5(a3, lane);
    a4 = wht5(a4, lane);
    a5 = wht5(a5, lane);
    a6 = wht5(a6, lane);

    float* o = out + e * NQ;
    if (lane == 17) o[0] = a0;                 // q0: L={4,0}
    if (lane == 8)  { o[1] = a1; o[7] = a3; }  // q1: L={3},J=8 ; q7: L={3},J=2
    if (lane == 20) o[2] = a2;                 // q2: L={4,2},J=4
    if (lane == 10) o[3] = a3;                 // q3: L={3,1},J=2
    if (lane == 5)  o[4] = a4;                 // q4: L={2,0},J=1
    if (lane == 2)  { o[5] = a5; o[9] = a6; }  // q5: L={1},J=8,H ; q9: L={1},H
    if (lane == 16) o[6] = a2;                 // q6: L={4},J=4
    if (lane == 4)  o[8] = a4;                 // q8: L={2},J=1
}

extern "C" void kernel_launch(void* const* d_in, const int* in_sizes, int n_in,
                              void* d_out, int out_size) {
    const float* x       = (const float*)d_in[0];  // (16384, 64)
    const float* Wm      = (const float*)d_in[1];  // (10, 64)
    const float* b       = (const float*)d_in[2];  // (10,)
    const float* weights = (const float*)d_in[3];  // (6, 10, 3)
    float* out = (float*)d_out;                    // (16384, 10)

    const int smem_bytes = (10970 + 16) * sizeof(float);
    cudaFuncSetAttribute(qsim_kernel,
                         cudaFuncAttributeMaxDynamicSharedMemorySize, smem_bytes);

    prep_kernel<<<1, 1024>>>(weights);
    qsim_kernel<<<BATCH / 8, 256, smem_bytes>>>(x, Wm, b, out);
}